// round 3
// baseline (speedup 1.0000x reference)
#include <cuda_runtime.h>
#include <cstdint>

#define NBLK 8
#define CH 256
#define ROWSTRIDE 2048
#define OUT_HALF 33554432u

// stage byte offsets (within one 48KB stage)
#define OFF_AR 0
#define OFF_AI 16384
#define OFF_WR 32768
#define OFF_WI 40960
#define STAGE_BYTES 49152
#define SMEM_BIAS 0          // 512 floats
#define SMEM_ST0  2048
#define SMEM_ALLOC (2048 + 2*STAGE_BYTES)   // 100352

__device__ float g_wT[2*NBLK*CH*CH];   // [sel][blk][n][k], K-major, tf32 RNA

// ---------------------------------------------------------------------------
__device__ __forceinline__ uint32_t smem_u32(const void* p){
    uint32_t r;
    asm("{ .reg .u64 t; cvta.to.shared.u64 t, %1; cvt.u32.u64 %0, t; }"
        : "=r"(r) : "l"(p));
    return r;
}
__device__ __forceinline__ void cpa16(uint32_t dst, const float* src){
    asm volatile("cp.async.cg.shared.global [%0], [%1], 16;"
                 :: "r"(dst), "l"(src) : "memory");
}
__device__ __forceinline__ void cp_commit(){ asm volatile("cp.async.commit_group;" ::: "memory"); }
__device__ __forceinline__ void cp_wait1(){ asm volatile("cp.async.wait_group 1;" ::: "memory"); }
__device__ __forceinline__ void cp_wait0(){ asm volatile("cp.async.wait_group 0;" ::: "memory"); }

__device__ __forceinline__ float lds_f(uint32_t a){
    float v; asm volatile("ld.shared.f32 %0, [%1];" : "=f"(v) : "r"(a)); return v;
}
__device__ __forceinline__ uint32_t lds_u(uint32_t a){
    uint32_t v; asm volatile("ld.shared.b32 %0, [%1];" : "=r"(v) : "r"(a)); return v;
}
__device__ __forceinline__ uint32_t f2tf(float v){
    uint32_t r; asm("cvt.rna.tf32.f32 %0, %1;" : "=r"(r) : "f"(v)); return r;
}
__device__ __forceinline__ void mma8(float* d, const uint32_t* a, const uint32_t* b){
    asm volatile(
        "mma.sync.aligned.m16n8k8.row.col.f32.tf32.tf32.f32 "
        "{%0,%1,%2,%3}, {%4,%5,%6,%7}, {%8,%9}, {%0,%1,%2,%3};"
        : "+f"(d[0]), "+f"(d[1]), "+f"(d[2]), "+f"(d[3])
        : "r"(a[0]), "r"(a[1]), "r"(a[2]), "r"(a[3]), "r"(b[0]), "r"(b[1]));
}

// ---------------------------------------------------------------------------
// Prep: w[b][k][n] -> g_wT[sel][b][n][k], RNA-rounded to tf32
// ---------------------------------------------------------------------------
__global__ void emm_prep(const float* __restrict__ wr, const float* __restrict__ wi){
    __shared__ float tile[32][33];
    int b = blockIdx.z & 7, sel = blockIdx.z >> 3;
    const float* s = (sel ? wi : wr) + (size_t)b*CH*CH;
    float* dst = g_wT + (size_t)sel*NBLK*CH*CH + (size_t)b*CH*CH;
    int k0 = blockIdx.x*32, n0 = blockIdx.y*32;
    int tx = threadIdx.x, ty = threadIdx.y;
    #pragma unroll
    for (int i = 0; i < 32; i += 8)
        tile[ty+i][tx] = s[(size_t)(k0+ty+i)*CH + (n0+tx)];
    __syncthreads();
    #pragma unroll
    for (int i = 0; i < 32; i += 8){
        uint32_t r; asm("cvt.rna.tf32.f32 %0, %1;" : "=r"(r) : "f"(tile[tx][ty+i]));
        dst[(size_t)(n0+ty+i)*CH + (k0+tx)] = __uint_as_float(r);
    }
}

// ---------------------------------------------------------------------------
// Stage load: A_r/A_i 128x32, W_r/W_i 64x32, XOR-swizzled 16B chunks
// ---------------------------------------------------------------------------
__device__ __forceinline__ void load_stage(
    const float* __restrict__ xr, const float* __restrict__ xi,
    uint32_t st, int m0, int blk, int n0, int k0, int tid)
{
    const float* wr = g_wT + ((size_t)blk*CH + n0)*CH;
    const float* wi = g_wT + ((size_t)(NBLK + blk)*CH + n0)*CH;
    #pragma unroll
    for (int i = 0; i < 4; i++){            // A: 1024 chunks each
        int c = tid + i*256;
        int row = c >> 3, c16 = c & 7;
        int sw = c16 ^ (row & 7);
        uint32_t d = st + (uint32_t)(row*128 + sw*16);
        size_t g = (size_t)(m0 + row)*ROWSTRIDE + blk*CH + k0 + c16*4;
        cpa16(d + OFF_AR, xr + g);
        cpa16(d + OFF_AI, xi + g);
    }
    #pragma unroll
    for (int i = 0; i < 2; i++){            // W: 512 chunks each
        int c = tid + i*256;
        int row = c >> 3, c16 = c & 7;
        int sw = c16 ^ (row & 7);
        uint32_t d = st + (uint32_t)(row*128 + sw*16);
        size_t g = (size_t)row*CH + k0 + c16*4;
        cpa16(d + OFF_WR, wr + g);
        cpa16(d + OFF_WI, wi + g);
    }
}

// swizzled float address within a tensor: row, 4-float chunk x (0..7), lane t
__device__ __forceinline__ uint32_t sw_addr(uint32_t base, int row, int x, int t){
    return base + (uint32_t)(row*128 + ((x ^ (row & 7))*16) + t*4);
}

// ---------------------------------------------------------------------------
__global__ void __launch_bounds__(256, 2) emm_main(
    const float* __restrict__ xr, const float* __restrict__ xi,
    const float* __restrict__ br, const float* __restrict__ bi,
    float* __restrict__ out)
{
    extern __shared__ char smem[];
    uint32_t sb = smem_u32(smem);
    int tid = threadIdx.x;
    int wid = tid >> 5, lid = tid & 31;
    int g = lid >> 2, t = lid & 3;
    int warp_m = wid >> 1, warp_n = wid & 1;

    int bx = blockIdx.x;
    int m0 = (bx >> 2) * 128;
    int n0 = (bx & 3) * 64;
    int blk = blockIdx.y;

    // bias -> smem
    float* bs = (float*)smem;
    bs[tid]       = br[blk*CH + tid];
    bs[tid + 256] = bi[blk*CH + tid];

    uint32_t st0 = sb + SMEM_ST0;
    uint32_t st1 = st0 + STAGE_BYTES;

    float dr[2][4][4], di[2][4][4];
    #pragma unroll
    for (int a = 0; a < 2; a++)
        #pragma unroll
        for (int b = 0; b < 4; b++)
            #pragma unroll
            for (int c = 0; c < 4; c++){ dr[a][b][c] = 0.f; di[a][b][c] = 0.f; }

    load_stage(xr, xi, st0, m0, blk, n0, 0, tid);  cp_commit();
    load_stage(xr, xi, st1, m0, blk, n0, 32, tid); cp_commit();

    #pragma unroll 1
    for (int kk = 0; kk < 8; kk++){
        uint32_t st = (kk & 1) ? st1 : st0;
        if (kk == 7) cp_wait0(); else cp_wait1();
        __syncthreads();

        #pragma unroll
        for (int s = 0; s < 4; s++){
            // B fragments for all 4 n-subtiles
            uint32_t fbr[4][2], fbi[4][2], fbn[4][2];
            #pragma unroll
            for (int nn = 0; nn < 4; nn++){
                int row = warp_n*32 + nn*8 + g;
                uint32_t a0 = sw_addr(st + OFF_WR, row, 2*s,   t);
                uint32_t a1 = sw_addr(st + OFF_WR, row, 2*s+1, t);
                fbr[nn][0] = lds_u(a0);
                fbr[nn][1] = lds_u(a1);
                fbi[nn][0] = lds_u(a0 + (OFF_WI - OFF_WR));
                fbi[nn][1] = lds_u(a1 + (OFF_WI - OFF_WR));
                fbn[nn][0] = fbi[nn][0] ^ 0x80000000u;
                fbn[nn][1] = fbi[nn][1] ^ 0x80000000u;
            }
            #pragma unroll
            for (int mm = 0; mm < 2; mm++){
                int r0 = warp_m*32 + mm*16;
                uint32_t far[4], fai[4];
                int rA = r0 + g, rB = r0 + g + 8;
                far[0] = f2tf(lds_f(sw_addr(st + OFF_AR, rA, 2*s,   t)));
                far[1] = f2tf(lds_f(sw_addr(st + OFF_AR, rB, 2*s,   t)));
                far[2] = f2tf(lds_f(sw_addr(st + OFF_AR, rA, 2*s+1, t)));
                far[3] = f2tf(lds_f(sw_addr(st + OFF_AR, rB, 2*s+1, t)));
                fai[0] = f2tf(lds_f(sw_addr(st + OFF_AI, rA, 2*s,   t)));
                fai[1] = f2tf(lds_f(sw_addr(st + OFF_AI, rB, 2*s,   t)));
                fai[2] = f2tf(lds_f(sw_addr(st + OFF_AI, rA, 2*s+1, t)));
                fai[3] = f2tf(lds_f(sw_addr(st + OFF_AI, rB, 2*s+1, t)));
                #pragma unroll
                for (int nn = 0; nn < 4; nn++){
                    mma8(dr[mm][nn], far, fbr[nn]);   // + r*wr
                    mma8(dr[mm][nn], fai, fbn[nn]);   // - i*wi
                    mma8(di[mm][nn], far, fbi[nn]);   // + r*wi
                    mma8(di[mm][nn], fai, fbr[nn]);   // + i*wr
                }
            }
        }
        __syncthreads();
        if (kk < 6){
            load_stage(xr, xi, st, m0, blk, n0, (kk + 2)*32, tid);
            cp_commit();
        }
    }

    // epilogue: bias + coalesced float2 stores (32B sectors per 4 lanes)
    float* o_r = out;
    float* o_i = out + OUT_HALF;
    #pragma unroll
    for (int mm = 0; mm < 2; mm++){
        int rowA = m0 + warp_m*32 + mm*16 + g;
        #pragma unroll
        for (int nn = 0; nn < 4; nn++){
            int cidx = n0 + warp_n*32 + nn*8 + 2*t;          // channel index
            size_t col = (size_t)blk*CH + cidx;
            float b0r = bs[cidx], b1r = bs[cidx+1];
            float b0i = bs[256+cidx], b1i = bs[256+cidx+1];
            size_t a0 = (size_t)rowA * ROWSTRIDE + col;
            size_t a1 = (size_t)(rowA + 8) * ROWSTRIDE + col;
            float2 v;
            v.x = dr[mm][nn][0] + b0r; v.y = dr[mm][nn][1] + b1r;
            *(float2*)(o_r + a0) = v;
            v.x = dr[mm][nn][2] + b0r; v.y = dr[mm][nn][3] + b1r;
            *(float2*)(o_r + a1) = v;
            v.x = di[mm][nn][0] + b0i; v.y = di[mm][nn][1] + b1i;
            *(float2*)(o_i + a0) = v;
            v.x = di[mm][nn][2] + b0i; v.y = di[mm][nn][3] + b1i;
            *(float2*)(o_i + a1) = v;
        }
    }
}

// ---------------------------------------------------------------------------
extern "C" void kernel_launch(void* const* d_in, const int* in_sizes, int n_in,
                              void* d_out, int out_size)
{
    const float* real = (const float*)d_in[0];
    const float* imag = (const float*)d_in[1];
    const float* w_r  = (const float*)d_in[2];
    const float* w_i  = (const float*)d_in[3];
    const float* b_r  = (const float*)d_in[4];
    const float* b_i  = (const float*)d_in[5];
    float* out = (float*)d_out;

    cudaFuncSetAttribute(emm_main,
        cudaFuncAttributeMaxDynamicSharedMemorySize, SMEM_ALLOC);

    emm_prep<<<dim3(8, 8, 16), dim3(32, 8)>>>(w_r, w_i);
    emm_main<<<dim3(512, 8), 256, SMEM_ALLOC>>>(real, imag, b_r, b_i, out);
}